// round 3
// baseline (speedup 1.0000x reference)
#include <cuda_runtime.h>

#define NN 50000
#define EE 1250000
#define DD 64
#define LL 3

// ---- scratch (static device allocations; referenced ONLY from device code) ----
__device__ float g_deg[NN];
__device__ float g_dis[NN];
__device__ float g_selfnorm[NN];
__device__ int   g_indeg[NN];
__device__ int   g_off[NN + 1];
__device__ int   g_cur[NN];
__device__ int   g_srow[EE];
__device__ float g_snorm[EE];
__device__ __align__(16) float g_h [NN * DD];
__device__ __align__(16) float g_x1[NN * DD];
__device__ __align__(16) float g_x2[NN * DD];

// ---------------------------------------------------------------------------
// 1) init degrees (self-loop fill = 2.0) and in-degree counters
__global__ void init_k() {
    int i = blockIdx.x * blockDim.x + threadIdx.x;
    if (i < NN) { g_deg[i] = 2.0f; g_indeg[i] = 0; }
}

// 2) accumulate weighted degree + integer in-degree per destination
__global__ void deg_k(const int* __restrict__ col,
                      const float* __restrict__ w) {
    int e = blockIdx.x * blockDim.x + threadIdx.x;
    if (e < EE) {
        int c = col[e];
        atomicAdd(&g_deg[c], w[e]);
        atomicAdd(&g_indeg[c], 1);
    }
}

// 3) dis = deg^{-1/2}; self-loop norm = dis*2*dis
__global__ void dis_k() {
    int i = blockIdx.x * blockDim.x + threadIdx.x;
    if (i < NN) {
        float d = g_deg[i];              // always >= 2.0
        float s = rsqrtf(d);
        g_dis[i] = s;
        g_selfnorm[i] = 2.0f * s * s;
    }
}

// 4) exclusive prefix sum of in-degrees -> CSR offsets (single block)
__global__ void scan_k() {
    const int T = 1024, CH = 49;       // 49*1024 = 50176 >= NN
    __shared__ int s[T];
    int t = threadIdx.x;
    int start = t * CH;
    int end = start + CH; if (end > NN) end = NN;
    int sum = 0;
    for (int i = start; i < end; ++i) sum += g_indeg[i];
    s[t] = sum;
    __syncthreads();
    // Hillis-Steele inclusive scan
    for (int off = 1; off < T; off <<= 1) {
        int v = (t >= off) ? s[t - off] : 0;
        __syncthreads();
        s[t] += v;
        __syncthreads();
    }
    int run = (t == 0) ? 0 : s[t - 1];
    for (int i = start; i < end; ++i) {
        g_off[i] = run;
        g_cur[i] = run;
        run += g_indeg[i];
    }
    if (t == T - 1) g_off[NN] = s[T - 1];
}

// 5) scatter edges into CSR (by destination); compute per-edge norm inline
__global__ void scatter_k(const int* __restrict__ row,
                          const int* __restrict__ col,
                          const float* __restrict__ w) {
    int e = blockIdx.x * blockDim.x + threadIdx.x;
    if (e < EE) {
        int r = row[e];
        int c = col[e];
        int p = atomicAdd(&g_cur[c], 1);
        g_srow[p]  = r;
        g_snorm[p] = g_dis[r] * w[e] * g_dis[c];
    }
}

// ---------------------------------------------------------------------------
// 6) H = X @ W   (50000 x 64 @ 64 x 64). src selector: 0=x(input), 1=g_x1, 2=g_x2
__global__ void __launch_bounds__(256) gemm_k(const float* __restrict__ xin,
                                              int src,
                                              const float* __restrict__ W) {
    const float* X = (src == 0) ? xin : ((src == 1) ? g_x1 : g_x2);

    __shared__ float xsT[64][64];   // xsT[k][r] (transposed tile)
    __shared__ float ws [64][64];   // ws[k][c]
    int tid = threadIdx.x;
    int rbase = blockIdx.x * 64;

    const float4* W4 = (const float4*)W;
    float4* ws4 = (float4*)&ws[0][0];
#pragma unroll
    for (int i = 0; i < 4; ++i) ws4[tid + i * 256] = W4[tid + i * 256];

    const float4* X4 = (const float4*)X;
#pragma unroll
    for (int i = 0; i < 4; ++i) {
        int idx4 = tid + i * 256;        // 0..1023 float4 of the 64x64 tile
        int r  = idx4 >> 4;              // 0..63
        int q  = idx4 & 15;              // float4 column group
        int gr = rbase + r;
        float4 v = (gr < NN) ? X4[gr * 16 + q] : make_float4(0.f, 0.f, 0.f, 0.f);
        int k0 = q << 2;
        xsT[k0    ][r] = v.x;
        xsT[k0 + 1][r] = v.y;
        xsT[k0 + 2][r] = v.z;
        xsT[k0 + 3][r] = v.w;
    }
    __syncthreads();

    int tx = tid & 15, ty = tid >> 4;
    int r0 = ty * 4, c0 = tx * 4;
    float acc[4][4] = {};
#pragma unroll
    for (int k = 0; k < 64; ++k) {
        float4 xv = *(const float4*)&xsT[k][r0];
        float4 wv = *(const float4*)&ws[k][c0];
        acc[0][0] += xv.x * wv.x; acc[0][1] += xv.x * wv.y; acc[0][2] += xv.x * wv.z; acc[0][3] += xv.x * wv.w;
        acc[1][0] += xv.y * wv.x; acc[1][1] += xv.y * wv.y; acc[1][2] += xv.y * wv.z; acc[1][3] += xv.y * wv.w;
        acc[2][0] += xv.z * wv.x; acc[2][1] += xv.z * wv.y; acc[2][2] += xv.z * wv.z; acc[2][3] += xv.z * wv.w;
        acc[3][0] += xv.w * wv.x; acc[3][1] += xv.w * wv.y; acc[3][2] += xv.w * wv.z; acc[3][3] += xv.w * wv.w;
    }

    float4* H4 = (float4*)g_h;
#pragma unroll
    for (int i = 0; i < 4; ++i) {
        int gr = rbase + r0 + i;
        if (gr < NN) {
            float4 o = make_float4(acc[i][0], acc[i][1], acc[i][2], acc[i][3]);
            H4[gr * 16 + (c0 >> 2)] = o;
        }
    }
}

// ---------------------------------------------------------------------------
// 7) gather-aggregate: one warp per node, float2 per lane, relu(agg + b)
//    dst selector: 1=g_x1, 2=g_x2
__global__ void __launch_bounds__(256) agg_k(const float* __restrict__ bias,
                                             int dst) {
    int node = blockIdx.x * 8 + (threadIdx.x >> 5);
    int lane = threadIdx.x & 31;
    if (node >= NN) return;

    const float2* H2 = (const float2*)g_h;
    float sn = g_selfnorm[node];
    float2 hv = H2[node * 32 + lane];
    float ax = hv.x * sn, ay = hv.y * sn;

    int s = g_off[node], e = g_off[node + 1];
    int p = s;
    for (; p + 1 < e; p += 2) {
        int   r1 = g_srow[p],     r2 = g_srow[p + 1];
        float n1 = g_snorm[p],    n2 = g_snorm[p + 1];
        float2 a = H2[r1 * 32 + lane];
        float2 b = H2[r2 * 32 + lane];
        ax += a.x * n1 + b.x * n2;
        ay += a.y * n1 + b.y * n2;
    }
    if (p < e) {
        int   r1 = g_srow[p];
        float n1 = g_snorm[p];
        float2 a = H2[r1 * 32 + lane];
        ax += a.x * n1;
        ay += a.y * n1;
    }

    float bx = bias[lane * 2], by = bias[lane * 2 + 1];
    float2 o;
    o.x = fmaxf(ax + bx, 0.f);
    o.y = fmaxf(ay + by, 0.f);
    float2* Y = (float2*)((dst == 1) ? g_x1 : g_x2);
    Y[node * 32 + lane] = o;
}

// ---------------------------------------------------------------------------
// 8) out[n] = dot(x[n,:], Wf) + bf  — one warp per node. src: 1=g_x1, 2=g_x2
__global__ void __launch_bounds__(256) final_k(int src,
                                               const float* __restrict__ Wf,
                                               const float* __restrict__ bf,
                                               float* __restrict__ out) {
    const float* X = (src == 1) ? g_x1 : g_x2;
    int node = blockIdx.x * 8 + (threadIdx.x >> 5);
    int lane = threadIdx.x & 31;
    if (node >= NN) return;
    float a = X[node * 64 + lane] * Wf[lane]
            + X[node * 64 + lane + 32] * Wf[lane + 32];
#pragma unroll
    for (int o = 16; o; o >>= 1) a += __shfl_down_sync(0xffffffffu, a, o);
    if (lane == 0) out[node] = a + bf[0];
}

// ---------------------------------------------------------------------------
extern "C" void kernel_launch(void* const* d_in, const int* in_sizes, int n_in,
                              void* d_out, int out_size) {
    const float* x  = (const float*)d_in[0];
    const int*   ei = (const int*)d_in[1];      // [2, E] (int32 on device)
    const float* ew = (const float*)d_in[2];
    const float* Ws = (const float*)d_in[3];    // [L, 64, 64]
    const float* bs = (const float*)d_in[4];    // [L, 64]
    const float* Wf = (const float*)d_in[5];    // [64, 1]
    const float* bf = (const float*)d_in[6];    // [1]
    float*       out = (float*)d_out;
    // d_in[7] = prob (unused, dropout p=0)

    const int* erow = ei;        // sources (x_j)
    const int* ecol = ei + EE;   // targets (aggregation)

    const int TB = 256;
    // graph normalization + CSR build (once, reused by all layers)
    init_k   <<<(NN + TB - 1) / TB, TB>>>();
    deg_k    <<<(EE + TB - 1) / TB, TB>>>(ecol, ew);
    dis_k    <<<(NN + TB - 1) / TB, TB>>>();
    scan_k   <<<1, 1024>>>();
    scatter_k<<<(EE + TB - 1) / TB, TB>>>(erow, ecol, ew);

    // layer 0: x -> g_h -> g_x1
    gemm_k<<<(NN + 63) / 64, 256>>>(x, 0, Ws + 0 * DD * DD);
    agg_k <<<NN / 8, 256>>>(bs + 0 * DD, 1);
    // layer 1: g_x1 -> g_h -> g_x2
    gemm_k<<<(NN + 63) / 64, 256>>>(x, 1, Ws + 1 * DD * DD);
    agg_k <<<NN / 8, 256>>>(bs + 1 * DD, 2);
    // layer 2: g_x2 -> g_h -> g_x1
    gemm_k<<<(NN + 63) / 64, 256>>>(x, 2, Ws + 2 * DD * DD);
    agg_k <<<NN / 8, 256>>>(bs + 2 * DD, 1);

    final_k<<<NN / 8, 256>>>(1, Wf, bf, out);
}

// round 4
// speedup vs baseline: 1.9995x; 1.9995x over previous
#include <cuda_runtime.h>

#define NN 50000
#define EE 1250000
#define DD 64
#define LL 3
#define SCAN_B 256
#define NBLK ((NN + SCAN_B - 1) / SCAN_B)   // 196

// ---- scratch (static device allocations; referenced ONLY from device code) ----
__device__ float g_deg[NN];
__device__ float g_dis[NN];
__device__ float g_selfnorm[NN];
__device__ int   g_indeg[NN];
__device__ int   g_off[NN + 1];
__device__ int   g_cur[NN];
__device__ int   g_bsum[NBLK];
__device__ int   g_bpre[NBLK];
__device__ int   g_srow[EE];
__device__ float g_snorm[EE];
__device__ __align__(16) float g_h [NN * DD];
__device__ __align__(16) float g_x1[NN * DD];
__device__ __align__(16) float g_x2[NN * DD];

// ---------------------------------------------------------------------------
// 1) init degrees (self-loop fill = 2.0) and in-degree counters
__global__ void init_k() {
    int i = blockIdx.x * blockDim.x + threadIdx.x;
    if (i < NN) { g_deg[i] = 2.0f; g_indeg[i] = 0; }
}

// 2) accumulate weighted degree + integer in-degree per destination
__global__ void deg_k(const int* __restrict__ col,
                      const float* __restrict__ w) {
    int e = blockIdx.x * blockDim.x + threadIdx.x;
    if (e < EE) {
        int c = col[e];
        atomicAdd(&g_deg[c], w[e]);
        atomicAdd(&g_indeg[c], 1);
    }
}

// 3) dis = deg^{-1/2}; self-loop norm = dis*2*dis
__global__ void dis_k() {
    int i = blockIdx.x * blockDim.x + threadIdx.x;
    if (i < NN) {
        float d = g_deg[i];              // always >= 2.0
        float s = rsqrtf(d);
        g_dis[i] = s;
        g_selfnorm[i] = 2.0f * s * s;
    }
}

// ---------------------------------------------------------------------------
// 4a) per-block sums of indeg (coalesced)
__global__ void scan_a() {
    __shared__ int s[SCAN_B];
    int t = threadIdx.x;
    int i = blockIdx.x * SCAN_B + t;
    int v = (i < NN) ? g_indeg[i] : 0;
    s[t] = v;
    __syncthreads();
#pragma unroll
    for (int off = SCAN_B / 2; off > 0; off >>= 1) {
        if (t < off) s[t] += s[t + off];
        __syncthreads();
    }
    if (t == 0) g_bsum[blockIdx.x] = s[0];
}

// 4b) single-block exclusive scan over block sums (NBLK = 196 <= 256)
__global__ void scan_b() {
    __shared__ int s[SCAN_B];
    int t = threadIdx.x;
    s[t] = (t < NBLK) ? g_bsum[t] : 0;
    __syncthreads();
    for (int off = 1; off < SCAN_B; off <<= 1) {
        int v = (t >= off) ? s[t - off] : 0;
        __syncthreads();
        s[t] += v;
        __syncthreads();
    }
    if (t < NBLK) g_bpre[t] = (t == 0) ? 0 : s[t - 1];   // exclusive
    if (t == 0) g_off[NN] = EE;   // total in-degree is exactly E
}

// 4c) per-block exclusive scan + block prefix -> g_off, g_cur (coalesced)
__global__ void scan_c() {
    __shared__ int s[SCAN_B];
    int t = threadIdx.x;
    int i = blockIdx.x * SCAN_B + t;
    int v = (i < NN) ? g_indeg[i] : 0;
    s[t] = v;
    __syncthreads();
    for (int off = 1; off < SCAN_B; off <<= 1) {
        int u = (t >= off) ? s[t - off] : 0;
        __syncthreads();
        s[t] += u;
        __syncthreads();
    }
    if (i < NN) {
        int excl = s[t] - v + g_bpre[blockIdx.x];   // inclusive - self = exclusive
        g_off[i] = excl;
        g_cur[i] = excl;
    }
}

// 5) scatter edges into CSR (by destination); compute per-edge norm inline
__global__ void scatter_k(const int* __restrict__ row,
                          const int* __restrict__ col,
                          const float* __restrict__ w) {
    int e = blockIdx.x * blockDim.x + threadIdx.x;
    if (e < EE) {
        int r = row[e];
        int c = col[e];
        int p = atomicAdd(&g_cur[c], 1);
        g_srow[p]  = r;
        g_snorm[p] = g_dis[r] * w[e] * g_dis[c];
    }
}

// ---------------------------------------------------------------------------
// 6) H = X @ W   (50000 x 64 @ 64 x 64). src selector: 0=x(input), 1=g_x1, 2=g_x2
__global__ void __launch_bounds__(256) gemm_k(const float* __restrict__ xin,
                                              int src,
                                              const float* __restrict__ W) {
    const float* X = (src == 0) ? xin : ((src == 1) ? g_x1 : g_x2);

    __shared__ float xsT[64][64];   // xsT[k][r] (transposed tile)
    __shared__ float ws [64][64];   // ws[k][c]
    int tid = threadIdx.x;
    int rbase = blockIdx.x * 64;

    const float4* W4 = (const float4*)W;
    float4* ws4 = (float4*)&ws[0][0];
#pragma unroll
    for (int i = 0; i < 4; ++i) ws4[tid + i * 256] = W4[tid + i * 256];

    const float4* X4 = (const float4*)X;
#pragma unroll
    for (int i = 0; i < 4; ++i) {
        int idx4 = tid + i * 256;        // 0..1023 float4 of the 64x64 tile
        int r  = idx4 >> 4;              // 0..63
        int q  = idx4 & 15;              // float4 column group
        int gr = rbase + r;
        float4 v = (gr < NN) ? X4[gr * 16 + q] : make_float4(0.f, 0.f, 0.f, 0.f);
        int k0 = q << 2;
        xsT[k0    ][r] = v.x;
        xsT[k0 + 1][r] = v.y;
        xsT[k0 + 2][r] = v.z;
        xsT[k0 + 3][r] = v.w;
    }
    __syncthreads();

    int tx = tid & 15, ty = tid >> 4;
    int r0 = ty * 4, c0 = tx * 4;
    float acc[4][4] = {};
#pragma unroll
    for (int k = 0; k < 64; ++k) {
        float4 xv = *(const float4*)&xsT[k][r0];
        float4 wv = *(const float4*)&ws[k][c0];
        acc[0][0] += xv.x * wv.x; acc[0][1] += xv.x * wv.y; acc[0][2] += xv.x * wv.z; acc[0][3] += xv.x * wv.w;
        acc[1][0] += xv.y * wv.x; acc[1][1] += xv.y * wv.y; acc[1][2] += xv.y * wv.z; acc[1][3] += xv.y * wv.w;
        acc[2][0] += xv.z * wv.x; acc[2][1] += xv.z * wv.y; acc[2][2] += xv.z * wv.z; acc[2][3] += xv.z * wv.w;
        acc[3][0] += xv.w * wv.x; acc[3][1] += xv.w * wv.y; acc[3][2] += xv.w * wv.z; acc[3][3] += xv.w * wv.w;
    }

    float4* H4 = (float4*)g_h;
#pragma unroll
    for (int i = 0; i < 4; ++i) {
        int gr = rbase + r0 + i;
        if (gr < NN) {
            float4 o = make_float4(acc[i][0], acc[i][1], acc[i][2], acc[i][3]);
            H4[gr * 16 + (c0 >> 2)] = o;
        }
    }
}

// ---------------------------------------------------------------------------
// 7) gather-aggregate: one warp per node, float2 per lane, relu(agg + b)
//    dst selector: 1=g_x1, 2=g_x2
__global__ void __launch_bounds__(256) agg_k(const float* __restrict__ bias,
                                             int dst) {
    int node = blockIdx.x * 8 + (threadIdx.x >> 5);
    int lane = threadIdx.x & 31;
    if (node >= NN) return;

    const float2* H2 = (const float2*)g_h;
    float sn = g_selfnorm[node];
    float2 hv = H2[node * 32 + lane];
    float ax = hv.x * sn, ay = hv.y * sn;

    int s = g_off[node], e = g_off[node + 1];
    int p = s;
    for (; p + 1 < e; p += 2) {
        int   r1 = g_srow[p],     r2 = g_srow[p + 1];
        float n1 = g_snorm[p],    n2 = g_snorm[p + 1];
        float2 a = H2[r1 * 32 + lane];
        float2 b = H2[r2 * 32 + lane];
        ax += a.x * n1 + b.x * n2;
        ay += a.y * n1 + b.y * n2;
    }
    if (p < e) {
        int   r1 = g_srow[p];
        float n1 = g_snorm[p];
        float2 a = H2[r1 * 32 + lane];
        ax += a.x * n1;
        ay += a.y * n1;
    }

    float bx = bias[lane * 2], by = bias[lane * 2 + 1];
    float2 o;
    o.x = fmaxf(ax + bx, 0.f);
    o.y = fmaxf(ay + by, 0.f);
    float2* Y = (float2*)((dst == 1) ? g_x1 : g_x2);
    Y[node * 32 + lane] = o;
}

// ---------------------------------------------------------------------------
// 8) out[n] = dot(x[n,:], Wf) + bf  — one warp per node. src: 1=g_x1, 2=g_x2
__global__ void __launch_bounds__(256) final_k(int src,
                                               const float* __restrict__ Wf,
                                               const float* __restrict__ bf,
                                               float* __restrict__ out) {
    const float* X = (src == 1) ? g_x1 : g_x2;
    int node = blockIdx.x * 8 + (threadIdx.x >> 5);
    int lane = threadIdx.x & 31;
    if (node >= NN) return;
    float a = X[node * 64 + lane] * Wf[lane]
            + X[node * 64 + lane + 32] * Wf[lane + 32];
#pragma unroll
    for (int o = 16; o; o >>= 1) a += __shfl_down_sync(0xffffffffu, a, o);
    if (lane == 0) out[node] = a + bf[0];
}

// ---------------------------------------------------------------------------
extern "C" void kernel_launch(void* const* d_in, const int* in_sizes, int n_in,
                              void* d_out, int out_size) {
    const float* x  = (const float*)d_in[0];
    const int*   ei = (const int*)d_in[1];      // [2, E] (int32 on device)
    const float* ew = (const float*)d_in[2];
    const float* Ws = (const float*)d_in[3];    // [L, 64, 64]
    const float* bs = (const float*)d_in[4];    // [L, 64]
    const float* Wf = (const float*)d_in[5];    // [64, 1]
    const float* bf = (const float*)d_in[6];    // [1]
    float*       out = (float*)d_out;
    // d_in[7] = prob (unused, dropout p=0)

    const int* erow = ei;        // sources (x_j)
    const int* ecol = ei + EE;   // targets (aggregation)

    const int TB = 256;
    // graph normalization + CSR build (once, reused by all layers)
    init_k   <<<(NN + TB - 1) / TB, TB>>>();
    deg_k    <<<(EE + TB - 1) / TB, TB>>>(ecol, ew);
    dis_k    <<<(NN + TB - 1) / TB, TB>>>();
    scan_a   <<<NBLK, SCAN_B>>>();
    scan_b   <<<1, SCAN_B>>>();
    scan_c   <<<NBLK, SCAN_B>>>();
    scatter_k<<<(EE + TB - 1) / TB, TB>>>(erow, ecol, ew);

    // layer 0: x -> g_h -> g_x1
    gemm_k<<<(NN + 63) / 64, 256>>>(x, 0, Ws + 0 * DD * DD);
    agg_k <<<NN / 8, 256>>>(bs + 0 * DD, 1);
    // layer 1: g_x1 -> g_h -> g_x2
    gemm_k<<<(NN + 63) / 64, 256>>>(x, 1, Ws + 1 * DD * DD);
    agg_k <<<NN / 8, 256>>>(bs + 1 * DD, 2);
    // layer 2: g_x2 -> g_h -> g_x1
    gemm_k<<<(NN + 63) / 64, 256>>>(x, 2, Ws + 2 * DD * DD);
    agg_k <<<NN / 8, 256>>>(bs + 2 * DD, 1);

    final_k<<<NN / 8, 256>>>(1, Wf, bf, out);
}